// round 9
// baseline (speedup 1.0000x reference)
#include <cuda_runtime.h>
#include <math.h>

#define BX   2
#define NSEQ 1024
#define HIDD 2048
#define HH   32
#define DD   64
#define HKV  8
#define NC   16
#define TS   65   // padded smem row stride (bank-conflict-free column access)

// ---------------- scratch (device globals; no allocs allowed) ----------------
__device__ float g_q    [BX*NSEQ*HIDD];      // [B,N,H*D]
__device__ float g_k    [BX*NSEQ*HKV*DD];    // [B,N,HKV*D]
__device__ float g_v    [BX*NSEQ*HKV*DD];
__device__ float g_kt   [BX*HKV*DD*NSEQ];    // [B,HKV,D,N] transposed K for coalesced scores
__device__ float g_ql   [BX*HH*NSEQ*DD];     // softmax(q) per head
__device__ float g_kl   [BX*HKV*NSEQ*DD];    // softmax(k) per kv head
__device__ float g_beta [BX*HKV*NSEQ*DD];    // log_sigmoid(k)/16
__device__ float g_u    [BX*HKV*NSEQ*DD];    // T @ v_beta
__device__ float g_w    [BX*HKV*NSEQ*DD];    // T @ k_beta
__device__ float g_ocomb[BX*NSEQ*HIDD];      // 0.5*o_base + 0.5*o_lin (pre-Wo)

// ---------------- generic fp32 SGEMM, 128x128 tile, BK=8, 256 thr ----------------
__global__ __launch_bounds__(256) void sgemm128(const float* __restrict__ A,
                                                const float* __restrict__ B,
                                                float* __restrict__ C,
                                                int M, int N, int K)
{
    __shared__ float As[8][128];
    __shared__ float Bs[8][128];
    int tid = threadIdx.x;
    int bx = blockIdx.x, by = blockIdx.y;
    int aRow = tid >> 1, aCol = (tid & 1) << 2;
    int bRow = tid >> 5, bCol = (tid & 31) << 2;
    const float* Ap = A + (size_t)(by*128 + aRow)*K + aCol;
    const float* Bp = B + (size_t)bRow*N + bx*128 + bCol;
    int tx = tid & 15, ty = tid >> 4;
    float acc[8][8];
    #pragma unroll
    for (int i = 0; i < 8; i++)
        #pragma unroll
        for (int j = 0; j < 8; j++) acc[i][j] = 0.f;

    for (int k0 = 0; k0 < K; k0 += 8) {
        float4 a4 = *(const float4*)Ap; Ap += 8;
        float4 b4 = *(const float4*)Bp; Bp += (size_t)8*N;
        As[aCol+0][aRow] = a4.x; As[aCol+1][aRow] = a4.y;
        As[aCol+2][aRow] = a4.z; As[aCol+3][aRow] = a4.w;
        *(float4*)&Bs[bRow][bCol] = b4;
        __syncthreads();
        #pragma unroll
        for (int kk = 0; kk < 8; kk++) {
            float4 a0 = *(const float4*)&As[kk][ty*8];
            float4 a1 = *(const float4*)&As[kk][ty*8+4];
            float4 b0 = *(const float4*)&Bs[kk][tx*8];
            float4 b1 = *(const float4*)&Bs[kk][tx*8+4];
            float ar[8] = {a0.x,a0.y,a0.z,a0.w,a1.x,a1.y,a1.z,a1.w};
            float br[8] = {b0.x,b0.y,b0.z,b0.w,b1.x,b1.y,b1.z,b1.w};
            #pragma unroll
            for (int i = 0; i < 8; i++)
                #pragma unroll
                for (int j = 0; j < 8; j++)
                    acc[i][j] += ar[i]*br[j];
        }
        __syncthreads();
    }
    float* Cp = C + (size_t)(by*128 + ty*8)*N + bx*128 + tx*8;
    #pragma unroll
    for (int i = 0; i < 8; i++) {
        *(float4*)(Cp + (size_t)i*N)     = make_float4(acc[i][0],acc[i][1],acc[i][2],acc[i][3]);
        *(float4*)(Cp + (size_t)i*N + 4) = make_float4(acc[i][4],acc[i][5],acc[i][6],acc[i][7]);
    }
}

// ---------------- q softmax: one warp per (b,i,h) row of D=64 ----------------
__global__ __launch_bounds__(256) void qsoftmax_kernel()
{
    int gw = blockIdx.x * 8 + (threadIdx.x >> 5);   // 65536 rows total
    int lane = threadIdx.x & 31;
    int h = gw & 31;
    int i = (gw >> 5) & 1023;
    int b = gw >> 15;
    const float* src = g_q + ((size_t)(b*NSEQ + i))*HIDD + h*DD;
    float x0 = src[lane], x1 = src[lane+32];
    float m = fmaxf(x0, x1);
    #pragma unroll
    for (int o = 16; o > 0; o >>= 1) m = fmaxf(m, __shfl_xor_sync(0xffffffffu, m, o));
    float e0 = __expf(x0 - m), e1 = __expf(x1 - m);
    float s = e0 + e1;
    #pragma unroll
    for (int o = 16; o > 0; o >>= 1) s += __shfl_xor_sync(0xffffffffu, s, o);
    float inv = 1.f / s;
    float* dst = g_ql + ((size_t)((b*HH + h)*NSEQ + i))*DD;
    dst[lane] = e0*inv; dst[lane+32] = e1*inv;
}

// --------- k prep: softmax(k), log_sigmoid(k)/16, and transpose into g_kt ---------
__global__ __launch_bounds__(256) void kprep_kernel()
{
    int gw = blockIdx.x * 8 + (threadIdx.x >> 5);   // 16384 rows: (b, i, kvh)
    int lane = threadIdx.x & 31;
    int kvh = gw & 7;
    int i = (gw >> 3) & 1023;
    int b = gw >> 13;
    const float* src = g_k + ((size_t)(b*NSEQ + i))*(HKV*DD) + kvh*DD;
    float x0 = src[lane], x1 = src[lane+32];
    float m = fmaxf(x0, x1);
    #pragma unroll
    for (int o = 16; o > 0; o >>= 1) m = fmaxf(m, __shfl_xor_sync(0xffffffffu, m, o));
    float e0 = __expf(x0 - m), e1 = __expf(x1 - m);
    float s = e0 + e1;
    #pragma unroll
    for (int o = 16; o > 0; o >>= 1) s += __shfl_xor_sync(0xffffffffu, s, o);
    float inv = 1.f / s;
    size_t base = ((size_t)((b*HKV + kvh)*NSEQ + i))*DD;
    g_kl[base + lane]      = e0*inv;
    g_kl[base + lane + 32] = e1*inv;
    // stable log-sigmoid: min(x,0) - log1p(exp(-|x|))
    float ls0 = fminf(x0, 0.f) - log1pf(__expf(-fabsf(x0)));
    float ls1 = fminf(x1, 0.f) - log1pf(__expf(-fabsf(x1)));
    g_beta[base + lane]      = ls0 * 0.0625f;
    g_beta[base + lane + 32] = ls1 * 0.0625f;
    // transposed raw k for the base-attention scores kernel
    size_t ktb = ((size_t)(b*HKV + kvh))*DD*NSEQ;
    g_kt[ktb + (size_t)lane*NSEQ + i]        = x0;
    g_kt[ktb + (size_t)(lane + 32)*NSEQ + i] = x1;
}

// -------- fused base attention: scores -> softmax -> attn_weights + o_base --------
// block = (query tile of 8 rows, h, b), 256 threads
__global__ __launch_bounds__(256) void attn_kernel(float* __restrict__ attn_out)
{
    __shared__ float qs[8][64];
    __shared__ float sc[8][1024];
    __shared__ float red[4][8][64];
    int b = blockIdx.z, h = blockIdx.y, it = blockIdx.x;
    int kvh = h >> 2;
    int i0 = it << 3;
    int tid = threadIdx.x;
    int jmax = i0 + 7;

    for (int idx = tid; idx < 8*64; idx += 256) {
        int r = idx >> 6, d = idx & 63;
        qs[r][d] = g_q[((size_t)(b*NSEQ + i0 + r))*HIDD + h*DD + d];
    }
    __syncthreads();

    // phase 1: scores (coalesced reads from transposed K)
    const float* ktb = g_kt + ((size_t)(b*HKV + kvh))*DD*NSEQ;
    const float scale = 0.125f;  // 1/sqrt(64)
    for (int j = tid; j <= jmax; j += 256) {
        float acc[8] = {0.f,0.f,0.f,0.f,0.f,0.f,0.f,0.f};
        const float* kcol = ktb + j;
        #pragma unroll 8
        for (int d = 0; d < 64; d++) {
            float kv = kcol[(size_t)d*NSEQ];
            #pragma unroll
            for (int r = 0; r < 8; r++) acc[r] += qs[r][d]*kv;
        }
        #pragma unroll
        for (int r = 0; r < 8; r++) sc[r][j] = acc[r]*scale;
    }
    __syncthreads();

    // phase 2: per-row softmax (warp w owns row w), write attn_weights
    {
        int w = tid >> 5, lane = tid & 31;
        int jlim = i0 + w;  // inclusive causal limit
        float m = -1e30f;
        for (int j = lane; j <= jlim; j += 32) m = fmaxf(m, sc[w][j]);
        #pragma unroll
        for (int o = 16; o > 0; o >>= 1) m = fmaxf(m, __shfl_xor_sync(0xffffffffu, m, o));
        float s = 0.f;
        for (int j = lane; j <= jlim; j += 32) { float e = __expf(sc[w][j]-m); sc[w][j] = e; s += e; }
        #pragma unroll
        for (int o = 16; o > 0; o >>= 1) s += __shfl_xor_sync(0xffffffffu, s, o);
        float inv = 1.f / s;
        for (int j = lane; j <= jlim; j += 32) sc[w][j] *= inv;
        for (int j = jlim+1+lane; j <= jmax; j += 32) sc[w][j] = 0.f;  // tile tail for phase 3
        if (attn_out) {
            float* ap = attn_out + ((size_t)((b*HH + h)*NSEQ + i0 + w))*NSEQ;
            for (int j = lane; j <= jlim; j += 32) ap[j] = sc[w][j];
            for (int j = jlim+1+lane; j < NSEQ; j += 32) ap[j] = 0.f;
        }
    }
    __syncthreads();

    // phase 3: o_base = P @ V, 4 j-slots x 64 d-lanes
    {
        int slot = tid >> 6, d = tid & 63;
        float acc[8] = {0.f,0.f,0.f,0.f,0.f,0.f,0.f,0.f};
        const float* vb = g_v + (size_t)b*NSEQ*(HKV*DD) + kvh*DD + d;
        for (int j = slot; j <= jmax; j += 4) {
            float vv = vb[(size_t)j*(HKV*DD)];
            #pragma unroll
            for (int r = 0; r < 8; r++) acc[r] += sc[r][j]*vv;
        }
        #pragma unroll
        for (int r = 0; r < 8; r++) red[slot][r][d] = acc[r];
    }
    __syncthreads();
    for (int idx = tid; idx < 512; idx += 256) {
        int r = idx >> 6, d = idx & 63;
        float o = red[0][r][d] + red[1][r][d] + red[2][r][d] + red[3][r][d];
        g_ocomb[((size_t)(b*NSEQ + i0 + r))*HIDD + h*DD + d] = 0.5f * o;  // (1-MAG)=0.5
    }
}

__device__ __forceinline__ void fma4x4(float a[4][4], const float x[4], const float y[4])
{
    #pragma unroll
    for (int r = 0; r < 4; r++)
        #pragma unroll
        for (int c = 0; c < 4; c++)
            a[r][c] += x[r]*y[c];
}

// -------- delta pre: per (b,kvh,chunk) compute u = T v_beta, w = T k_beta --------
__global__ __launch_bounds__(256) void delta_pre_kernel()
{
    extern __shared__ float sm[];
    float* kc = sm;            // 64 x TS
    float* kb = kc + 64*TS;
    float* vb = kb + 64*TS;
    float* L  = vb + 64*TS;
    int blk = blockIdx.x;      // b*128 + kvh*16 + c
    int b = blk >> 7, kvh = (blk >> 4) & 7, c = blk & 15;
    int tid = threadIdx.x;
    int j0 = c << 6;
    const float* klp = g_kl   + ((size_t)((b*HKV + kvh)*NSEQ + j0))*DD;
    const float* bp  = g_beta + ((size_t)((b*HKV + kvh)*NSEQ + j0))*DD;
    const float* vp  = g_v    + ((size_t)(b*NSEQ + j0))*(HKV*DD) + kvh*DD;
    for (int idx = tid; idx < 4096; idx += 256) {
        int i = idx >> 6, d = idx & 63;
        float kk = klp[idx];
        float bb = bp[idx];
        kc[i*TS+d] = kk;
        kb[i*TS+d] = kk*bb;
        vb[i*TS+d] = vp[(size_t)i*(HKV*DD) + d]*bb;
    }
    __syncthreads();
    // L = k_beta @ k^T (full; solve uses only strict lower)
    {
        int ti = (tid >> 4) << 2, tj = (tid & 15) << 2;
        float a[4][4];
        #pragma unroll
        for (int r = 0; r < 4; r++) { a[r][0]=a[r][1]=a[r][2]=a[r][3]=0.f; }
        for (int d = 0; d < 64; d++) {
            float x[4], y[4];
            #pragma unroll
            for (int r = 0; r < 4; r++) x[r] = kb[(ti+r)*TS+d];
            #pragma unroll
            for (int cc = 0; cc < 4; cc++) y[cc] = kc[(tj+cc)*TS+d];
            fma4x4(a, x, y);
        }
        #pragma unroll
        for (int r = 0; r < 4; r++)
            #pragma unroll
            for (int cc = 0; cc < 4; cc++)
                L[(ti+r)*TS + tj + cc] = a[r][cc];
    }
    __syncthreads();
    // forward substitution (unit lower): X[i] -= sum_{j<i} L[i][j] X[j], X in {vb, kb}
    {
        int arr = tid >> 6;
        int d = tid & 63;
        float* X = (arr == 0) ? vb : kb;
        for (int i = 1; i < 64; i++) {
            if (arr < 2) {
                const float* Li = L + i*TS;
                float a0 = 0.f, a1 = 0.f;
                int j = 0;
                for (; j + 1 < i; j += 2) {
                    a0 += Li[j]   * X[j*TS + d];
                    a1 += Li[j+1] * X[(j+1)*TS + d];
                }
                if (j < i) a0 += Li[j] * X[j*TS + d];
                X[i*TS + d] -= (a0 + a1);
            }
            __syncthreads();
        }
    }
    float* uo = g_u + ((size_t)((b*HKV + kvh)*NSEQ + j0))*DD;
    float* wo = g_w + ((size_t)((b*HKV + kvh)*NSEQ + j0))*DD;
    for (int idx = tid; idx < 4096; idx += 256) {
        int i = idx >> 6, d = idx & 63;
        uo[idx] = vb[i*TS+d];
        wo[idx] = kb[i*TS+d];
    }
}

// -------- delta scan: per (b,h) sequential over 16 chunks, accumulates into ocomb --------
__global__ __launch_bounds__(256) void delta_scan_kernel()
{
    extern __shared__ float sm[];
    float* S  = sm;            // state [d][e]
    float* qc = S  + 64*TS;
    float* kc = qc + 64*TS;
    float* wa = kc + 64*TS;    // w tile, reused as attn
    float* up = wa + 64*TS;    // u tile, updated in place to u_p
    int b = blockIdx.x >> 5;
    int h = blockIdx.x & 31;
    int kvh = h >> 2;
    int tid = threadIdx.x;
    int ti = (tid >> 4) << 2, tj = (tid & 15) << 2;

    for (int idx = tid; idx < 64*TS; idx += 256) S[idx] = 0.f;

    for (int c = 0; c < NC; c++) {
        int j0 = c << 6;
        const float* qp = g_ql + ((size_t)((b*HH  + h  )*NSEQ + j0))*DD;
        const float* kp = g_kl + ((size_t)((b*HKV + kvh)*NSEQ + j0))*DD;
        const float* uu = g_u  + ((size_t)((b*HKV + kvh)*NSEQ + j0))*DD;
        const float* ww = g_w  + ((size_t)((b*HKV + kvh)*NSEQ + j0))*DD;
        __syncthreads();
        for (int idx = tid; idx < 4096; idx += 256) {
            int i = idx >> 6, d = idx & 63;
            qc[i*TS+d] = qp[idx];
            kc[i*TS+d] = kp[idx];
            wa[i*TS+d] = ww[idx];
            up[i*TS+d] = uu[idx];
        }
        __syncthreads();
        // u_p = u - w @ S   (thread owns [ti..ti+3] x [tj..tj+3], in-place on up)
        {
            float a[4][4];
            #pragma unroll
            for (int r = 0; r < 4; r++) { a[r][0]=a[r][1]=a[r][2]=a[r][3]=0.f; }
            for (int d = 0; d < 64; d++) {
                float x[4], y[4];
                #pragma unroll
                for (int r = 0; r < 4; r++) x[r] = wa[(ti+r)*TS+d];
                #pragma unroll
                for (int cc = 0; cc < 4; cc++) y[cc] = S[d*TS+tj+cc];
                fma4x4(a, x, y);
            }
            #pragma unroll
            for (int r = 0; r < 4; r++)
                #pragma unroll
                for (int cc = 0; cc < 4; cc++)
                    up[(ti+r)*TS + tj + cc] -= a[r][cc];
        }
        __syncthreads();
        // attn = tril(q @ k^T) into wa
        {
            float a[4][4];
            #pragma unroll
            for (int r = 0; r < 4; r++) { a[r][0]=a[r][1]=a[r][2]=a[r][3]=0.f; }
            for (int d = 0; d < 64; d++) {
                float x[4], y[4];
                #pragma unroll
                for (int r = 0; r < 4; r++) x[r] = qc[(ti+r)*TS+d];
                #pragma unroll
                for (int cc = 0; cc < 4; cc++) y[cc] = kc[(tj+cc)*TS+d];
                fma4x4(a, x, y);
            }
            #pragma unroll
            for (int r = 0; r < 4; r++)
                #pragma unroll
                for (int cc = 0; cc < 4; cc++)
                    wa[(ti+r)*TS + tj + cc] = ((tj+cc) <= (ti+r)) ? a[r][cc] : 0.f;
        }
        __syncthreads();
        // o = q @ S + attn @ u_p ; ocomb += MAG * o
        {
            float a[4][4];
            #pragma unroll
            for (int r = 0; r < 4; r++) { a[r][0]=a[r][1]=a[r][2]=a[r][3]=0.f; }
            for (int d = 0; d < 64; d++) {
                float x[4], y[4];
                #pragma unroll
                for (int r = 0; r < 4; r++) x[r] = qc[(ti+r)*TS+d];
                #pragma unroll
                for (int cc = 0; cc < 4; cc++) y[cc] = S[d*TS+tj+cc];
                fma4x4(a, x, y);
            }
            for (int j = 0; j < 64; j++) {
                float x[4], y[4];
                #pragma unroll
                for (int r = 0; r < 4; r++) x[r] = wa[(ti+r)*TS+j];
                #pragma unroll
                for (int cc = 0; cc < 4; cc++) y[cc] = up[j*TS+tj+cc];
                fma4x4(a, x, y);
            }
            #pragma unroll
            for (int r = 0; r < 4; r++)
                #pragma unroll
                for (int cc = 0; cc < 4; cc++) {
                    float* p = g_ocomb + ((size_t)(b*NSEQ + j0 + ti + r))*HIDD + h*DD + tj + cc;
                    *p = *p + 0.5f * a[r][cc];   // MAG = 0.5
                }
        }
        __syncthreads();
        // S += k^T @ u_p
        {
            float a[4][4];
            #pragma unroll
            for (int r = 0; r < 4; r++) { a[r][0]=a[r][1]=a[r][2]=a[r][3]=0.f; }
            for (int cc2 = 0; cc2 < 64; cc2++) {
                float x[4], y[4];
                #pragma unroll
                for (int r = 0; r < 4; r++) x[r] = kc[cc2*TS + ti + r];
                #pragma unroll
                for (int cc = 0; cc < 4; cc++) y[cc] = up[cc2*TS + tj + cc];
                fma4x4(a, x, y);
            }
            #pragma unroll
            for (int r = 0; r < 4; r++)
                #pragma unroll
                for (int cc = 0; cc < 4; cc++)
                    S[(ti+r)*TS + tj + cc] += a[r][cc];
        }
    }
}

// ---------------- launch ----------------
extern "C" void kernel_launch(void* const* d_in, const int* in_sizes, int n_in,
                              void* d_out, int out_size)
{
    const float* hidden = (const float*)d_in[0];
    const float* Wq = (const float*)d_in[1];
    const float* Wk = (const float*)d_in[2];
    const float* Wv = (const float*)d_in[3];
    const float* Wo = (const float*)d_in[4];
    float* out = (float*)d_out;

    float *pq, *pk, *pv, *pocomb;
    cudaGetSymbolAddress((void**)&pq, g_q);
    cudaGetSymbolAddress((void**)&pk, g_k);
    cudaGetSymbolAddress((void**)&pv, g_v);
    cudaGetSymbolAddress((void**)&pocomb, g_ocomb);

    const long long OUT_E  = (long long)BX*NSEQ*HIDD;          // 4194304
    const long long ATTN_E = (long long)BX*HH*NSEQ*NSEQ;       // 67108864
    float* attn_out = nullptr;
    if ((long long)out_size >= OUT_E + ATTN_E) attn_out = out + OUT_E;

    cudaFuncSetAttribute(delta_pre_kernel,  cudaFuncAttributeMaxDynamicSharedMemorySize, 4*64*TS*4);
    cudaFuncSetAttribute(delta_scan_kernel, cudaFuncAttributeMaxDynamicSharedMemorySize, 5*64*TS*4);

    // 1. projections
    sgemm128<<<dim3(HIDD/128,   (BX*NSEQ)/128), 256>>>(hidden, Wq, pq, BX*NSEQ, HIDD,   HIDD);
    sgemm128<<<dim3((HKV*DD)/128,(BX*NSEQ)/128), 256>>>(hidden, Wk, pk, BX*NSEQ, HKV*DD, HIDD);
    sgemm128<<<dim3((HKV*DD)/128,(BX*NSEQ)/128), 256>>>(hidden, Wv, pv, BX*NSEQ, HKV*DD, HIDD);

    // 2. elementwise prep
    qsoftmax_kernel<<<(BX*NSEQ*HH)/8, 256>>>();
    kprep_kernel<<<(BX*NSEQ*HKV)/8, 256>>>();

    // 3. base attention (writes attn_weights + 0.5*o_base into ocomb)
    attn_kernel<<<dim3(NSEQ/8, HH, BX), 256>>>(attn_out);

    // 4. delta rule: parallel solve, then sequential scan (adds 0.5*o_lin into ocomb)
    delta_pre_kernel<<<BX*HKV*NC, 256, 4*64*TS*4>>>();
    delta_scan_kernel<<<BX*HH, 256, 5*64*TS*4>>>();

    // 5. output projection: out = (0.5*o_lin + 0.5*o_base) @ Wo
    sgemm128<<<dim3(HIDD/128, (BX*NSEQ)/128), 256>>>(pocomb, Wo, out, BX*NSEQ, HIDD, HIDD);
}

// round 10
// speedup vs baseline: 1.0025x; 1.0025x over previous
#include <cuda_runtime.h>
#include <math.h>

#define BX   2
#define NSEQ 1024
#define HIDD 2048
#define HH   32
#define DD   64
#define HKV  8
#define NC   16
#define TS   65   // padded smem row stride (bank-conflict-free column access)

// ---------------- scratch (device globals; no allocs allowed) ----------------
__device__ float g_q    [BX*NSEQ*HIDD];      // [B,N,H*D]
__device__ float g_k    [BX*NSEQ*HKV*DD];    // [B,N,HKV*D]
__device__ float g_v    [BX*NSEQ*HKV*DD];
__device__ float g_kt   [BX*HKV*DD*NSEQ];    // [B,HKV,D,N] transposed K for coalesced scores
__device__ float g_ql   [BX*HH*NSEQ*DD];     // softmax(q) per head
__device__ float g_kl   [BX*HKV*NSEQ*DD];    // softmax(k) per kv head
__device__ float g_beta [BX*HKV*NSEQ*DD];    // log_sigmoid(k)/16
__device__ float g_u    [BX*HKV*NSEQ*DD];    // T @ v_beta
__device__ float g_w    [BX*HKV*NSEQ*DD];    // T @ k_beta
__device__ float g_ocomb[BX*NSEQ*HIDD];      // 0.5*o_base + 0.5*o_lin (pre-Wo)

// ---------------- generic fp32 SGEMM, 128x128 tile, BK=8, 256 thr ----------------
__global__ __launch_bounds__(256) void sgemm128(const float* __restrict__ A,
                                                const float* __restrict__ B,
                                                float* __restrict__ C,
                                                int M, int N, int K)
{
    __shared__ float As[8][128];
    __shared__ float Bs[8][128];
    int tid = threadIdx.x;
    int bx = blockIdx.x, by = blockIdx.y;
    int aRow = tid >> 1, aCol = (tid & 1) << 2;
    int bRow = tid >> 5, bCol = (tid & 31) << 2;
    const float* Ap = A + (size_t)(by*128 + aRow)*K + aCol;
    const float* Bp = B + (size_t)bRow*N + bx*128 + bCol;
    int tx = tid & 15, ty = tid >> 4;
    float acc[8][8];
    #pragma unroll
    for (int i = 0; i < 8; i++)
        #pragma unroll
        for (int j = 0; j < 8; j++) acc[i][j] = 0.f;

    for (int k0 = 0; k0 < K; k0 += 8) {
        float4 a4 = *(const float4*)Ap; Ap += 8;
        float4 b4 = *(const float4*)Bp; Bp += (size_t)8*N;
        As[aCol+0][aRow] = a4.x; As[aCol+1][aRow] = a4.y;
        As[aCol+2][aRow] = a4.z; As[aCol+3][aRow] = a4.w;
        *(float4*)&Bs[bRow][bCol] = b4;
        __syncthreads();
        #pragma unroll
        for (int kk = 0; kk < 8; kk++) {
            float4 a0 = *(const float4*)&As[kk][ty*8];
            float4 a1 = *(const float4*)&As[kk][ty*8+4];
            float4 b0 = *(const float4*)&Bs[kk][tx*8];
            float4 b1 = *(const float4*)&Bs[kk][tx*8+4];
            float ar[8] = {a0.x,a0.y,a0.z,a0.w,a1.x,a1.y,a1.z,a1.w};
            float br[8] = {b0.x,b0.y,b0.z,b0.w,b1.x,b1.y,b1.z,b1.w};
            #pragma unroll
            for (int i = 0; i < 8; i++)
                #pragma unroll
                for (int j = 0; j < 8; j++)
                    acc[i][j] += ar[i]*br[j];
        }
        __syncthreads();
    }
    float* Cp = C + (size_t)(by*128 + ty*8)*N + bx*128 + tx*8;
    #pragma unroll
    for (int i = 0; i < 8; i++) {
        *(float4*)(Cp + (size_t)i*N)     = make_float4(acc[i][0],acc[i][1],acc[i][2],acc[i][3]);
        *(float4*)(Cp + (size_t)i*N + 4) = make_float4(acc[i][4],acc[i][5],acc[i][6],acc[i][7]);
    }
}

// ---------------- q softmax: one warp per (b,i,h) row of D=64 ----------------
__global__ __launch_bounds__(256) void qsoftmax_kernel()
{
    int gw = blockIdx.x * 8 + (threadIdx.x >> 5);   // 65536 rows total
    int lane = threadIdx.x & 31;
    int h = gw & 31;
    int i = (gw >> 5) & 1023;
    int b = gw >> 15;
    const float* src = g_q + ((size_t)(b*NSEQ + i))*HIDD + h*DD;
    float x0 = src[lane], x1 = src[lane+32];
    float m = fmaxf(x0, x1);
    #pragma unroll
    for (int o = 16; o > 0; o >>= 1) m = fmaxf(m, __shfl_xor_sync(0xffffffffu, m, o));
    float e0 = __expf(x0 - m), e1 = __expf(x1 - m);
    float s = e0 + e1;
    #pragma unroll
    for (int o = 16; o > 0; o >>= 1) s += __shfl_xor_sync(0xffffffffu, s, o);
    float inv = 1.f / s;
    float* dst = g_ql + ((size_t)((b*HH + h)*NSEQ + i))*DD;
    dst[lane] = e0*inv; dst[lane+32] = e1*inv;
}

// --------- k prep: softmax(k), log_sigmoid(k)/16, and transpose into g_kt ---------
__global__ __launch_bounds__(256) void kprep_kernel()
{
    int gw = blockIdx.x * 8 + (threadIdx.x >> 5);   // 16384 rows: (b, i, kvh)
    int lane = threadIdx.x & 31;
    int kvh = gw & 7;
    int i = (gw >> 3) & 1023;
    int b = gw >> 13;
    const float* src = g_k + ((size_t)(b*NSEQ + i))*(HKV*DD) + kvh*DD;
    float x0 = src[lane], x1 = src[lane+32];
    float m = fmaxf(x0, x1);
    #pragma unroll
    for (int o = 16; o > 0; o >>= 1) m = fmaxf(m, __shfl_xor_sync(0xffffffffu, m, o));
    float e0 = __expf(x0 - m), e1 = __expf(x1 - m);
    float s = e0 + e1;
    #pragma unroll
    for (int o = 16; o > 0; o >>= 1) s += __shfl_xor_sync(0xffffffffu, s, o);
    float inv = 1.f / s;
    size_t base = ((size_t)((b*HKV + kvh)*NSEQ + i))*DD;
    g_kl[base + lane]      = e0*inv;
    g_kl[base + lane + 32] = e1*inv;
    // stable log-sigmoid: min(x,0) - log1p(exp(-|x|))
    float ls0 = fminf(x0, 0.f) - log1pf(__expf(-fabsf(x0)));
    float ls1 = fminf(x1, 0.f) - log1pf(__expf(-fabsf(x1)));
    g_beta[base + lane]      = ls0 * 0.0625f;
    g_beta[base + lane + 32] = ls1 * 0.0625f;
    // transposed raw k for the base-attention scores kernel
    size_t ktb = ((size_t)(b*HKV + kvh))*DD*NSEQ;
    g_kt[ktb + (size_t)lane*NSEQ + i]        = x0;
    g_kt[ktb + (size_t)(lane + 32)*NSEQ + i] = x1;
}

// -------- fused base attention: scores -> softmax -> attn_weights + o_base --------
// block = (query tile of 8 rows, h, b), 256 threads
__global__ __launch_bounds__(256) void attn_kernel(float* __restrict__ attn_out)
{
    __shared__ float qs[8][64];
    __shared__ float sc[8][1024];
    __shared__ float red[4][8][64];
    int b = blockIdx.z, h = blockIdx.y, it = blockIdx.x;
    int kvh = h >> 2;
    int i0 = it << 3;
    int tid = threadIdx.x;
    int jmax = i0 + 7;

    for (int idx = tid; idx < 8*64; idx += 256) {
        int r = idx >> 6, d = idx & 63;
        qs[r][d] = g_q[((size_t)(b*NSEQ + i0 + r))*HIDD + h*DD + d];
    }
    __syncthreads();

    // phase 1: scores (coalesced reads from transposed K)
    const float* ktb = g_kt + ((size_t)(b*HKV + kvh))*DD*NSEQ;
    const float scale = 0.125f;  // 1/sqrt(64)
    for (int j = tid; j <= jmax; j += 256) {
        float acc[8] = {0.f,0.f,0.f,0.f,0.f,0.f,0.f,0.f};
        const float* kcol = ktb + j;
        #pragma unroll 8
        for (int d = 0; d < 64; d++) {
            float kv = kcol[(size_t)d*NSEQ];
            #pragma unroll
            for (int r = 0; r < 8; r++) acc[r] += qs[r][d]*kv;
        }
        #pragma unroll
        for (int r = 0; r < 8; r++) sc[r][j] = acc[r]*scale;
    }
    __syncthreads();

    // phase 2: per-row softmax (warp w owns row w), write attn_weights
    {
        int w = tid >> 5, lane = tid & 31;
        int jlim = i0 + w;  // inclusive causal limit
        float m = -1e30f;
        for (int j = lane; j <= jlim; j += 32) m = fmaxf(m, sc[w][j]);
        #pragma unroll
        for (int o = 16; o > 0; o >>= 1) m = fmaxf(m, __shfl_xor_sync(0xffffffffu, m, o));
        float s = 0.f;
        for (int j = lane; j <= jlim; j += 32) { float e = __expf(sc[w][j]-m); sc[w][j] = e; s += e; }
        #pragma unroll
        for (int o = 16; o > 0; o >>= 1) s += __shfl_xor_sync(0xffffffffu, s, o);
        float inv = 1.f / s;
        for (int j = lane; j <= jlim; j += 32) sc[w][j] *= inv;
        for (int j = jlim+1+lane; j <= jmax; j += 32) sc[w][j] = 0.f;  // tile tail for phase 3
        if (attn_out) {
            float* ap = attn_out + ((size_t)((b*HH + h)*NSEQ + i0 + w))*NSEQ;
            for (int j = lane; j <= jlim; j += 32) ap[j] = sc[w][j];
            for (int j = jlim+1+lane; j < NSEQ; j += 32) ap[j] = 0.f;
        }
    }
    __syncthreads();

    // phase 3: o_base = P @ V, 4 j-slots x 64 d-lanes
    {
        int slot = tid >> 6, d = tid & 63;
        float acc[8] = {0.f,0.f,0.f,0.f,0.f,0.f,0.f,0.f};
        const float* vb = g_v + (size_t)b*NSEQ*(HKV*DD) + kvh*DD + d;
        for (int j = slot; j <= jmax; j += 4) {
            float vv = vb[(size_t)j*(HKV*DD)];
            #pragma unroll
            for (int r = 0; r < 8; r++) acc[r] += sc[r][j]*vv;
        }
        #pragma unroll
        for (int r = 0; r < 8; r++) red[slot][r][d] = acc[r];
    }
    __syncthreads();
    for (int idx = tid; idx < 512; idx += 256) {
        int r = idx >> 6, d = idx & 63;
        float o = red[0][r][d] + red[1][r][d] + red[2][r][d] + red[3][r][d];
        g_ocomb[((size_t)(b*NSEQ + i0 + r))*HIDD + h*DD + d] = 0.5f * o;  // (1-MAG)=0.5
    }
}

__device__ __forceinline__ void fma4x4(float a[4][4], const float x[4], const float y[4])
{
    #pragma unroll
    for (int r = 0; r < 4; r++)
        #pragma unroll
        for (int c = 0; c < 4; c++)
            a[r][c] += x[r]*y[c];
}

// -------- delta pre: per (b,kvh,chunk) compute u = T v_beta, w = T k_beta --------
__global__ __launch_bounds__(256) void delta_pre_kernel()
{
    extern __shared__ float sm[];
    float* kc = sm;            // 64 x TS
    float* kb = kc + 64*TS;
    float* vb = kb + 64*TS;
    float* L  = vb + 64*TS;
    int blk = blockIdx.x;      // b*128 + kvh*16 + c
    int b = blk >> 7, kvh = (blk >> 4) & 7, c = blk & 15;
    int tid = threadIdx.x;
    int j0 = c << 6;
    const float* klp = g_kl   + ((size_t)((b*HKV + kvh)*NSEQ + j0))*DD;
    const float* bp  = g_beta + ((size_t)((b*HKV + kvh)*NSEQ + j0))*DD;
    const float* vp  = g_v    + ((size_t)(b*NSEQ + j0))*(HKV*DD) + kvh*DD;
    for (int idx = tid; idx < 4096; idx += 256) {
        int i = idx >> 6, d = idx & 63;
        float kk = klp[idx];
        float bb = bp[idx];
        kc[i*TS+d] = kk;
        kb[i*TS+d] = kk*bb;
        vb[i*TS+d] = vp[(size_t)i*(HKV*DD) + d]*bb;
    }
    __syncthreads();
    // L = k_beta @ k^T (full; solve uses only strict lower)
    {
        int ti = (tid >> 4) << 2, tj = (tid & 15) << 2;
        float a[4][4];
        #pragma unroll
        for (int r = 0; r < 4; r++) { a[r][0]=a[r][1]=a[r][2]=a[r][3]=0.f; }
        for (int d = 0; d < 64; d++) {
            float x[4], y[4];
            #pragma unroll
            for (int r = 0; r < 4; r++) x[r] = kb[(ti+r)*TS+d];
            #pragma unroll
            for (int cc = 0; cc < 4; cc++) y[cc] = kc[(tj+cc)*TS+d];
            fma4x4(a, x, y);
        }
        #pragma unroll
        for (int r = 0; r < 4; r++)
            #pragma unroll
            for (int cc = 0; cc < 4; cc++)
                L[(ti+r)*TS + tj + cc] = a[r][cc];
    }
    __syncthreads();
    // forward substitution (unit lower): X[i] -= sum_{j<i} L[i][j] X[j], X in {vb, kb}
    {
        int arr = tid >> 6;
        int d = tid & 63;
        float* X = (arr == 0) ? vb : kb;
        for (int i = 1; i < 64; i++) {
            if (arr < 2) {
                const float* Li = L + i*TS;
                float a0 = 0.f, a1 = 0.f;
                int j = 0;
                for (; j + 1 < i; j += 2) {
                    a0 += Li[j]   * X[j*TS + d];
                    a1 += Li[j+1] * X[(j+1)*TS + d];
                }
                if (j < i) a0 += Li[j] * X[j*TS + d];
                X[i*TS + d] -= (a0 + a1);
            }
            __syncthreads();
        }
    }
    float* uo = g_u + ((size_t)((b*HKV + kvh)*NSEQ + j0))*DD;
    float* wo = g_w + ((size_t)((b*HKV + kvh)*NSEQ + j0))*DD;
    for (int idx = tid; idx < 4096; idx += 256) {
        int i = idx >> 6, d = idx & 63;
        uo[idx] = vb[i*TS+d];
        wo[idx] = kb[i*TS+d];
    }
}

// -------- delta scan: per (b,h) sequential over 16 chunks, accumulates into ocomb --------
__global__ __launch_bounds__(256) void delta_scan_kernel()
{
    extern __shared__ float sm[];
    float* S  = sm;            // state [d][e]
    float* qc = S  + 64*TS;
    float* kc = qc + 64*TS;
    float* wa = kc + 64*TS;    // w tile, reused as attn
    float* up = wa + 64*TS;    // u tile, updated in place to u_p
    int b = blockIdx.x >> 5;
    int h = blockIdx.x & 31;
    int kvh = h >> 2;
    int tid = threadIdx.x;
    int ti = (tid >> 4) << 2, tj = (tid & 15) << 2;

    for (int idx = tid; idx < 64*TS; idx += 256) S[idx] = 0.f;

    for (int c = 0; c < NC; c++) {
        int j0 = c << 6;
        const float* qp = g_ql + ((size_t)((b*HH  + h  )*NSEQ + j0))*DD;
        const float* kp = g_kl + ((size_t)((b*HKV + kvh)*NSEQ + j0))*DD;
        const float* uu = g_u  + ((size_t)((b*HKV + kvh)*NSEQ + j0))*DD;
        const float* ww = g_w  + ((size_t)((b*HKV + kvh)*NSEQ + j0))*DD;
        __syncthreads();
        for (int idx = tid; idx < 4096; idx += 256) {
            int i = idx >> 6, d = idx & 63;
            qc[i*TS+d] = qp[idx];
            kc[i*TS+d] = kp[idx];
            wa[i*TS+d] = ww[idx];
            up[i*TS+d] = uu[idx];
        }
        __syncthreads();
        // u_p = u - w @ S   (thread owns [ti..ti+3] x [tj..tj+3], in-place on up)
        {
            float a[4][4];
            #pragma unroll
            for (int r = 0; r < 4; r++) { a[r][0]=a[r][1]=a[r][2]=a[r][3]=0.f; }
            for (int d = 0; d < 64; d++) {
                float x[4], y[4];
                #pragma unroll
                for (int r = 0; r < 4; r++) x[r] = wa[(ti+r)*TS+d];
                #pragma unroll
                for (int cc = 0; cc < 4; cc++) y[cc] = S[d*TS+tj+cc];
                fma4x4(a, x, y);
            }
            #pragma unroll
            for (int r = 0; r < 4; r++)
                #pragma unroll
                for (int cc = 0; cc < 4; cc++)
                    up[(ti+r)*TS + tj + cc] -= a[r][cc];
        }
        __syncthreads();
        // attn = tril(q @ k^T) into wa
        {
            float a[4][4];
            #pragma unroll
            for (int r = 0; r < 4; r++) { a[r][0]=a[r][1]=a[r][2]=a[r][3]=0.f; }
            for (int d = 0; d < 64; d++) {
                float x[4], y[4];
                #pragma unroll
                for (int r = 0; r < 4; r++) x[r] = qc[(ti+r)*TS+d];
                #pragma unroll
                for (int cc = 0; cc < 4; cc++) y[cc] = kc[(tj+cc)*TS+d];
                fma4x4(a, x, y);
            }
            #pragma unroll
            for (int r = 0; r < 4; r++)
                #pragma unroll
                for (int cc = 0; cc < 4; cc++)
                    wa[(ti+r)*TS + tj + cc] = ((tj+cc) <= (ti+r)) ? a[r][cc] : 0.f;
        }
        __syncthreads();
        // o = q @ S + attn @ u_p ; ocomb += MAG * o
        {
            float a[4][4];
            #pragma unroll
            for (int r = 0; r < 4; r++) { a[r][0]=a[r][1]=a[r][2]=a[r][3]=0.f; }
            for (int d = 0; d < 64; d++) {
                float x[4], y[4];
                #pragma unroll
                for (int r = 0; r < 4; r++) x[r] = qc[(ti+r)*TS+d];
                #pragma unroll
                for (int cc = 0; cc < 4; cc++) y[cc] = S[d*TS+tj+cc];
                fma4x4(a, x, y);
            }
            for (int j = 0; j < 64; j++) {
                float x[4], y[4];
                #pragma unroll
                for (int r = 0; r < 4; r++) x[r] = wa[(ti+r)*TS+j];
                #pragma unroll
                for (int cc = 0; cc < 4; cc++) y[cc] = up[j*TS+tj+cc];
                fma4x4(a, x, y);
            }
            #pragma unroll
            for (int r = 0; r < 4; r++)
                #pragma unroll
                for (int cc = 0; cc < 4; cc++) {
                    float* p = g_ocomb + ((size_t)(b*NSEQ + j0 + ti + r))*HIDD + h*DD + tj + cc;
                    *p = *p + 0.5f * a[r][cc];   // MAG = 0.5
                }
        }
        __syncthreads();
        // S += k^T @ u_p
        {
            float a[4][4];
            #pragma unroll
            for (int r = 0; r < 4; r++) { a[r][0]=a[r][1]=a[r][2]=a[r][3]=0.f; }
            for (int cc2 = 0; cc2 < 64; cc2++) {
                float x[4], y[4];
                #pragma unroll
                for (int r = 0; r < 4; r++) x[r] = kc[cc2*TS + ti + r];
                #pragma unroll
                for (int cc = 0; cc < 4; cc++) y[cc] = up[cc2*TS + tj + cc];
                fma4x4(a, x, y);
            }
            #pragma unroll
            for (int r = 0; r < 4; r++)
                #pragma unroll
                for (int cc = 0; cc < 4; cc++)
                    S[(ti+r)*TS + tj + cc] += a[r][cc];
        }
    }
}

// ---------------- launch ----------------
extern "C" void kernel_launch(void* const* d_in, const int* in_sizes, int n_in,
                              void* d_out, int out_size)
{
    const float* hidden = (const float*)d_in[0];
    const float* Wq = (const float*)d_in[1];
    const float* Wk = (const float*)d_in[2];
    const float* Wv = (const float*)d_in[3];
    const float* Wo = (const float*)d_in[4];
    float* out = (float*)d_out;

    float *pq, *pk, *pv, *pocomb;
    cudaGetSymbolAddress((void**)&pq, g_q);
    cudaGetSymbolAddress((void**)&pk, g_k);
    cudaGetSymbolAddress((void**)&pv, g_v);
    cudaGetSymbolAddress((void**)&pocomb, g_ocomb);

    const long long OUT_E  = (long long)BX*NSEQ*HIDD;          // 4194304
    const long long ATTN_E = (long long)BX*HH*NSEQ*NSEQ;       // 67108864
    float* attn_out = nullptr;
    if ((long long)out_size >= OUT_E + ATTN_E) attn_out = out + OUT_E;

    cudaFuncSetAttribute(delta_pre_kernel,  cudaFuncAttributeMaxDynamicSharedMemorySize, 4*64*TS*4);
    cudaFuncSetAttribute(delta_scan_kernel, cudaFuncAttributeMaxDynamicSharedMemorySize, 5*64*TS*4);

    // 1. projections
    sgemm128<<<dim3(HIDD/128,   (BX*NSEQ)/128), 256>>>(hidden, Wq, pq, BX*NSEQ, HIDD,   HIDD);
    sgemm128<<<dim3((HKV*DD)/128,(BX*NSEQ)/128), 256>>>(hidden, Wk, pk, BX*NSEQ, HKV*DD, HIDD);
    sgemm128<<<dim3((HKV*DD)/128,(BX*NSEQ)/128), 256>>>(hidden, Wv, pv, BX*NSEQ, HKV*DD, HIDD);

    // 2. elementwise prep
    qsoftmax_kernel<<<(BX*NSEQ*HH)/8, 256>>>();
    kprep_kernel<<<(BX*NSEQ*HKV)/8, 256>>>();

    // 3. base attention (writes attn_weights + 0.5*o_base into ocomb)
    attn_kernel<<<dim3(NSEQ/8, HH, BX), 256>>>(attn_out);

    // 4. delta rule: parallel solve, then sequential scan (adds 0.5*o_lin into ocomb)
    delta_pre_kernel<<<BX*HKV*NC, 256, 4*64*TS*4>>>();
    delta_scan_kernel<<<BX*HH, 256, 5*64*TS*4>>>();

    // 5. output projection: out = (0.5*o_lin + 0.5*o_base) @ Wo
    sgemm128<<<dim3(HIDD/128, (BX*NSEQ)/128), 256>>>(pocomb, Wo, out, BX*NSEQ, HIDD, HIDD);
}

// round 11
// speedup vs baseline: 1.0069x; 1.0044x over previous
#include <cuda_runtime.h>
#include <math.h>

#define BX   2
#define NSEQ 1024
#define HIDD 2048
#define HH   32
#define DD   64
#define HKV  8
#define NC   16
#define TS   65   // padded smem row stride (bank-conflict-free column access)

// ---------------- scratch (device globals; no allocs allowed) ----------------
__device__ float g_q    [BX*NSEQ*HIDD];      // [B,N,H*D]
__device__ float g_k    [BX*NSEQ*HKV*DD];    // [B,N,HKV*D]
__device__ float g_v    [BX*NSEQ*HKV*DD];
__device__ float g_kt   [BX*HKV*DD*NSEQ];    // [B,HKV,D,N] transposed K for coalesced scores
__device__ float g_ql   [BX*HH*NSEQ*DD];     // softmax(q) per head
__device__ float g_kl   [BX*HKV*NSEQ*DD];    // softmax(k) per kv head
__device__ float g_beta [BX*HKV*NSEQ*DD];    // log_sigmoid(k)/16
__device__ float g_u    [BX*HKV*NSEQ*DD];    // T @ v_beta
__device__ float g_w    [BX*HKV*NSEQ*DD];    // T @ k_beta
__device__ float g_ocomb[BX*NSEQ*HIDD];      // 0.5*o_base + 0.5*o_lin (pre-Wo)

// ---------------- generic fp32 SGEMM, 128x128 tile, BK=8, 256 thr ----------------
__global__ __launch_bounds__(256) void sgemm128(const float* __restrict__ A,
                                                const float* __restrict__ B,
                                                float* __restrict__ C,
                                                int M, int N, int K)
{
    __shared__ float As[8][128];
    __shared__ float Bs[8][128];
    int tid = threadIdx.x;
    int bx = blockIdx.x, by = blockIdx.y;
    int aRow = tid >> 1, aCol = (tid & 1) << 2;
    int bRow = tid >> 5, bCol = (tid & 31) << 2;
    const float* Ap = A + (size_t)(by*128 + aRow)*K + aCol;
    const float* Bp = B + (size_t)bRow*N + bx*128 + bCol;
    int tx = tid & 15, ty = tid >> 4;
    float acc[8][8];
    #pragma unroll
    for (int i = 0; i < 8; i++)
        #pragma unroll
        for (int j = 0; j < 8; j++) acc[i][j] = 0.f;

    for (int k0 = 0; k0 < K; k0 += 8) {
        float4 a4 = *(const float4*)Ap; Ap += 8;
        float4 b4 = *(const float4*)Bp; Bp += (size_t)8*N;
        As[aCol+0][aRow] = a4.x; As[aCol+1][aRow] = a4.y;
        As[aCol+2][aRow] = a4.z; As[aCol+3][aRow] = a4.w;
        *(float4*)&Bs[bRow][bCol] = b4;
        __syncthreads();
        #pragma unroll
        for (int kk = 0; kk < 8; kk++) {
            float4 a0 = *(const float4*)&As[kk][ty*8];
            float4 a1 = *(const float4*)&As[kk][ty*8+4];
            float4 b0 = *(const float4*)&Bs[kk][tx*8];
            float4 b1 = *(const float4*)&Bs[kk][tx*8+4];
            float ar[8] = {a0.x,a0.y,a0.z,a0.w,a1.x,a1.y,a1.z,a1.w};
            float br[8] = {b0.x,b0.y,b0.z,b0.w,b1.x,b1.y,b1.z,b1.w};
            #pragma unroll
            for (int i = 0; i < 8; i++)
                #pragma unroll
                for (int j = 0; j < 8; j++)
                    acc[i][j] += ar[i]*br[j];
        }
        __syncthreads();
    }
    float* Cp = C + (size_t)(by*128 + ty*8)*N + bx*128 + tx*8;
    #pragma unroll
    for (int i = 0; i < 8; i++) {
        *(float4*)(Cp + (size_t)i*N)     = make_float4(acc[i][0],acc[i][1],acc[i][2],acc[i][3]);
        *(float4*)(Cp + (size_t)i*N + 4) = make_float4(acc[i][4],acc[i][5],acc[i][6],acc[i][7]);
    }
}

// ---------------- q softmax: one warp per (b,i,h) row of D=64 ----------------
__global__ __launch_bounds__(256) void qsoftmax_kernel()
{
    int gw = blockIdx.x * 8 + (threadIdx.x >> 5);   // 65536 rows total
    int lane = threadIdx.x & 31;
    int h = gw & 31;
    int i = (gw >> 5) & 1023;
    int b = gw >> 15;
    const float* src = g_q + ((size_t)(b*NSEQ + i))*HIDD + h*DD;
    float x0 = src[lane], x1 = src[lane+32];
    float m = fmaxf(x0, x1);
    #pragma unroll
    for (int o = 16; o > 0; o >>= 1) m = fmaxf(m, __shfl_xor_sync(0xffffffffu, m, o));
    float e0 = __expf(x0 - m), e1 = __expf(x1 - m);
    float s = e0 + e1;
    #pragma unroll
    for (int o = 16; o > 0; o >>= 1) s += __shfl_xor_sync(0xffffffffu, s, o);
    float inv = 1.f / s;
    float* dst = g_ql + ((size_t)((b*HH + h)*NSEQ + i))*DD;
    dst[lane] = e0*inv; dst[lane+32] = e1*inv;
}

// --------- k prep: softmax(k), log_sigmoid(k)/16, and transpose into g_kt ---------
__global__ __launch_bounds__(256) void kprep_kernel()
{
    int gw = blockIdx.x * 8 + (threadIdx.x >> 5);   // 16384 rows: (b, i, kvh)
    int lane = threadIdx.x & 31;
    int kvh = gw & 7;
    int i = (gw >> 3) & 1023;
    int b = gw >> 13;
    const float* src = g_k + ((size_t)(b*NSEQ + i))*(HKV*DD) + kvh*DD;
    float x0 = src[lane], x1 = src[lane+32];
    float m = fmaxf(x0, x1);
    #pragma unroll
    for (int o = 16; o > 0; o >>= 1) m = fmaxf(m, __shfl_xor_sync(0xffffffffu, m, o));
    float e0 = __expf(x0 - m), e1 = __expf(x1 - m);
    float s = e0 + e1;
    #pragma unroll
    for (int o = 16; o > 0; o >>= 1) s += __shfl_xor_sync(0xffffffffu, s, o);
    float inv = 1.f / s;
    size_t base = ((size_t)((b*HKV + kvh)*NSEQ + i))*DD;
    g_kl[base + lane]      = e0*inv;
    g_kl[base + lane + 32] = e1*inv;
    // stable log-sigmoid: min(x,0) - log1p(exp(-|x|))
    float ls0 = fminf(x0, 0.f) - log1pf(__expf(-fabsf(x0)));
    float ls1 = fminf(x1, 0.f) - log1pf(__expf(-fabsf(x1)));
    g_beta[base + lane]      = ls0 * 0.0625f;
    g_beta[base + lane + 32] = ls1 * 0.0625f;
    // transposed raw k for the base-attention scores kernel
    size_t ktb = ((size_t)(b*HKV + kvh))*DD*NSEQ;
    g_kt[ktb + (size_t)lane*NSEQ + i]        = x0;
    g_kt[ktb + (size_t)(lane + 32)*NSEQ + i] = x1;
}

// -------- fused base attention: scores -> softmax -> attn_weights + o_base --------
// block = (query tile of 8 rows, h, b), 256 threads
__global__ __launch_bounds__(256) void attn_kernel(float* __restrict__ attn_out)
{
    __shared__ float qs[8][64];
    __shared__ float sc[8][1024];
    __shared__ float red[4][8][64];
    int b = blockIdx.z, h = blockIdx.y, it = blockIdx.x;
    int kvh = h >> 2;
    int i0 = it << 3;
    int tid = threadIdx.x;
    int jmax = i0 + 7;

    for (int idx = tid; idx < 8*64; idx += 256) {
        int r = idx >> 6, d = idx & 63;
        qs[r][d] = g_q[((size_t)(b*NSEQ + i0 + r))*HIDD + h*DD + d];
    }
    __syncthreads();

    // phase 1: scores (coalesced reads from transposed K)
    const float* ktb = g_kt + ((size_t)(b*HKV + kvh))*DD*NSEQ;
    const float scale = 0.125f;  // 1/sqrt(64)
    for (int j = tid; j <= jmax; j += 256) {
        float acc[8] = {0.f,0.f,0.f,0.f,0.f,0.f,0.f,0.f};
        const float* kcol = ktb + j;
        #pragma unroll 8
        for (int d = 0; d < 64; d++) {
            float kv = kcol[(size_t)d*NSEQ];
            #pragma unroll
            for (int r = 0; r < 8; r++) acc[r] += qs[r][d]*kv;
        }
        #pragma unroll
        for (int r = 0; r < 8; r++) sc[r][j] = acc[r]*scale;
    }
    __syncthreads();

    // phase 2: per-row softmax (warp w owns row w), write attn_weights
    {
        int w = tid >> 5, lane = tid & 31;
        int jlim = i0 + w;  // inclusive causal limit
        float m = -1e30f;
        for (int j = lane; j <= jlim; j += 32) m = fmaxf(m, sc[w][j]);
        #pragma unroll
        for (int o = 16; o > 0; o >>= 1) m = fmaxf(m, __shfl_xor_sync(0xffffffffu, m, o));
        float s = 0.f;
        for (int j = lane; j <= jlim; j += 32) { float e = __expf(sc[w][j]-m); sc[w][j] = e; s += e; }
        #pragma unroll
        for (int o = 16; o > 0; o >>= 1) s += __shfl_xor_sync(0xffffffffu, s, o);
        float inv = 1.f / s;
        for (int j = lane; j <= jlim; j += 32) sc[w][j] *= inv;
        for (int j = jlim+1+lane; j <= jmax; j += 32) sc[w][j] = 0.f;  // tile tail for phase 3
        if (attn_out) {
            float* ap = attn_out + ((size_t)((b*HH + h)*NSEQ + i0 + w))*NSEQ;
            for (int j = lane; j <= jlim; j += 32) ap[j] = sc[w][j];
            for (int j = jlim+1+lane; j < NSEQ; j += 32) ap[j] = 0.f;
        }
    }
    __syncthreads();

    // phase 3: o_base = P @ V, 4 j-slots x 64 d-lanes
    {
        int slot = tid >> 6, d = tid & 63;
        float acc[8] = {0.f,0.f,0.f,0.f,0.f,0.f,0.f,0.f};
        const float* vb = g_v + (size_t)b*NSEQ*(HKV*DD) + kvh*DD + d;
        for (int j = slot; j <= jmax; j += 4) {
            float vv = vb[(size_t)j*(HKV*DD)];
            #pragma unroll
            for (int r = 0; r < 8; r++) acc[r] += sc[r][j]*vv;
        }
        #pragma unroll
        for (int r = 0; r < 8; r++) red[slot][r][d] = acc[r];
    }
    __syncthreads();
    for (int idx = tid; idx < 512; idx += 256) {
        int r = idx >> 6, d = idx & 63;
        float o = red[0][r][d] + red[1][r][d] + red[2][r][d] + red[3][r][d];
        g_ocomb[((size_t)(b*NSEQ + i0 + r))*HIDD + h*DD + d] = 0.5f * o;  // (1-MAG)=0.5
    }
}

__device__ __forceinline__ void fma4x4(float a[4][4], const float x[4], const float y[4])
{
    #pragma unroll
    for (int r = 0; r < 4; r++)
        #pragma unroll
        for (int c = 0; c < 4; c++)
            a[r][c] += x[r]*y[c];
}

// -------- delta pre: per (b,kvh,chunk) compute u = T v_beta, w = T k_beta --------
__global__ __launch_bounds__(256) void delta_pre_kernel()
{
    extern __shared__ float sm[];
    float* kc = sm;            // 64 x TS
    float* kb = kc + 64*TS;
    float* vb = kb + 64*TS;
    float* L  = vb + 64*TS;
    int blk = blockIdx.x;      // b*128 + kvh*16 + c
    int b = blk >> 7, kvh = (blk >> 4) & 7, c = blk & 15;
    int tid = threadIdx.x;
    int j0 = c << 6;
    const float* klp = g_kl   + ((size_t)((b*HKV + kvh)*NSEQ + j0))*DD;
    const float* bp  = g_beta + ((size_t)((b*HKV + kvh)*NSEQ + j0))*DD;
    const float* vp  = g_v    + ((size_t)(b*NSEQ + j0))*(HKV*DD) + kvh*DD;
    for (int idx = tid; idx < 4096; idx += 256) {
        int i = idx >> 6, d = idx & 63;
        float kk = klp[idx];
        float bb = bp[idx];
        kc[i*TS+d] = kk;
        kb[i*TS+d] = kk*bb;
        vb[i*TS+d] = vp[(size_t)i*(HKV*DD) + d]*bb;
    }
    __syncthreads();
    // L = k_beta @ k^T (full; solve uses only strict lower)
    {
        int ti = (tid >> 4) << 2, tj = (tid & 15) << 2;
        float a[4][4];
        #pragma unroll
        for (int r = 0; r < 4; r++) { a[r][0]=a[r][1]=a[r][2]=a[r][3]=0.f; }
        for (int d = 0; d < 64; d++) {
            float x[4], y[4];
            #pragma unroll
            for (int r = 0; r < 4; r++) x[r] = kb[(ti+r)*TS+d];
            #pragma unroll
            for (int cc = 0; cc < 4; cc++) y[cc] = kc[(tj+cc)*TS+d];
            fma4x4(a, x, y);
        }
        #pragma unroll
        for (int r = 0; r < 4; r++)
            #pragma unroll
            for (int cc = 0; cc < 4; cc++)
                L[(ti+r)*TS + tj + cc] = a[r][cc];
    }
    __syncthreads();
    // forward substitution (unit lower): X[i] -= sum_{j<i} L[i][j] X[j], X in {vb, kb}
    {
        int arr = tid >> 6;
        int d = tid & 63;
        float* X = (arr == 0) ? vb : kb;
        for (int i = 1; i < 64; i++) {
            if (arr < 2) {
                const float* Li = L + i*TS;
                float a0 = 0.f, a1 = 0.f;
                int j = 0;
                for (; j + 1 < i; j += 2) {
                    a0 += Li[j]   * X[j*TS + d];
                    a1 += Li[j+1] * X[(j+1)*TS + d];
                }
                if (j < i) a0 += Li[j] * X[j*TS + d];
                X[i*TS + d] -= (a0 + a1);
            }
            __syncthreads();
        }
    }
    float* uo = g_u + ((size_t)((b*HKV + kvh)*NSEQ + j0))*DD;
    float* wo = g_w + ((size_t)((b*HKV + kvh)*NSEQ + j0))*DD;
    for (int idx = tid; idx < 4096; idx += 256) {
        int i = idx >> 6, d = idx & 63;
        uo[idx] = vb[i*TS+d];
        wo[idx] = kb[i*TS+d];
    }
}

// -------- delta scan: per (b,h) sequential over 16 chunks, accumulates into ocomb --------
__global__ __launch_bounds__(256) void delta_scan_kernel()
{
    extern __shared__ float sm[];
    float* S  = sm;            // state [d][e]
    float* qc = S  + 64*TS;
    float* kc = qc + 64*TS;
    float* wa = kc + 64*TS;    // w tile, reused as attn
    float* up = wa + 64*TS;    // u tile, updated in place to u_p
    int b = blockIdx.x >> 5;
    int h = blockIdx.x & 31;
    int kvh = h >> 2;
    int tid = threadIdx.x;
    int ti = (tid >> 4) << 2, tj = (tid & 15) << 2;

    for (int idx = tid; idx < 64*TS; idx += 256) S[idx] = 0.f;

    for (int c = 0; c < NC; c++) {
        int j0 = c << 6;
        const float* qp = g_ql + ((size_t)((b*HH  + h  )*NSEQ + j0))*DD;
        const float* kp = g_kl + ((size_t)((b*HKV + kvh)*NSEQ + j0))*DD;
        const float* uu = g_u  + ((size_t)((b*HKV + kvh)*NSEQ + j0))*DD;
        const float* ww = g_w  + ((size_t)((b*HKV + kvh)*NSEQ + j0))*DD;
        __syncthreads();
        for (int idx = tid; idx < 4096; idx += 256) {
            int i = idx >> 6, d = idx & 63;
            qc[i*TS+d] = qp[idx];
            kc[i*TS+d] = kp[idx];
            wa[i*TS+d] = ww[idx];
            up[i*TS+d] = uu[idx];
        }
        __syncthreads();
        // u_p = u - w @ S   (thread owns [ti..ti+3] x [tj..tj+3], in-place on up)
        {
            float a[4][4];
            #pragma unroll
            for (int r = 0; r < 4; r++) { a[r][0]=a[r][1]=a[r][2]=a[r][3]=0.f; }
            for (int d = 0; d < 64; d++) {
                float x[4], y[4];
                #pragma unroll
                for (int r = 0; r < 4; r++) x[r] = wa[(ti+r)*TS+d];
                #pragma unroll
                for (int cc = 0; cc < 4; cc++) y[cc] = S[d*TS+tj+cc];
                fma4x4(a, x, y);
            }
            #pragma unroll
            for (int r = 0; r < 4; r++)
                #pragma unroll
                for (int cc = 0; cc < 4; cc++)
                    up[(ti+r)*TS + tj + cc] -= a[r][cc];
        }
        __syncthreads();
        // attn = tril(q @ k^T) into wa
        {
            float a[4][4];
            #pragma unroll
            for (int r = 0; r < 4; r++) { a[r][0]=a[r][1]=a[r][2]=a[r][3]=0.f; }
            for (int d = 0; d < 64; d++) {
                float x[4], y[4];
                #pragma unroll
                for (int r = 0; r < 4; r++) x[r] = qc[(ti+r)*TS+d];
                #pragma unroll
                for (int cc = 0; cc < 4; cc++) y[cc] = kc[(tj+cc)*TS+d];
                fma4x4(a, x, y);
            }
            #pragma unroll
            for (int r = 0; r < 4; r++)
                #pragma unroll
                for (int cc = 0; cc < 4; cc++)
                    wa[(ti+r)*TS + tj + cc] = ((tj+cc) <= (ti+r)) ? a[r][cc] : 0.f;
        }
        __syncthreads();
        // o = q @ S + attn @ u_p ; ocomb += MAG * o
        {
            float a[4][4];
            #pragma unroll
            for (int r = 0; r < 4; r++) { a[r][0]=a[r][1]=a[r][2]=a[r][3]=0.f; }
            for (int d = 0; d < 64; d++) {
                float x[4], y[4];
                #pragma unroll
                for (int r = 0; r < 4; r++) x[r] = qc[(ti+r)*TS+d];
                #pragma unroll
                for (int cc = 0; cc < 4; cc++) y[cc] = S[d*TS+tj+cc];
                fma4x4(a, x, y);
            }
            for (int j = 0; j < 64; j++) {
                float x[4], y[4];
                #pragma unroll
                for (int r = 0; r < 4; r++) x[r] = wa[(ti+r)*TS+j];
                #pragma unroll
                for (int cc = 0; cc < 4; cc++) y[cc] = up[j*TS+tj+cc];
                fma4x4(a, x, y);
            }
            #pragma unroll
            for (int r = 0; r < 4; r++)
                #pragma unroll
                for (int cc = 0; cc < 4; cc++) {
                    float* p = g_ocomb + ((size_t)(b*NSEQ + j0 + ti + r))*HIDD + h*DD + tj + cc;
                    *p = *p + 0.5f * a[r][cc];   // MAG = 0.5
                }
        }
        __syncthreads();
        // S += k^T @ u_p
        {
            float a[4][4];
            #pragma unroll
            for (int r = 0; r < 4; r++) { a[r][0]=a[r][1]=a[r][2]=a[r][3]=0.f; }
            for (int cc2 = 0; cc2 < 64; cc2++) {
                float x[4], y[4];
                #pragma unroll
                for (int r = 0; r < 4; r++) x[r] = kc[cc2*TS + ti + r];
                #pragma unroll
                for (int cc = 0; cc < 4; cc++) y[cc] = up[cc2*TS + tj + cc];
                fma4x4(a, x, y);
            }
            #pragma unroll
            for (int r = 0; r < 4; r++)
                #pragma unroll
                for (int cc = 0; cc < 4; cc++)
                    S[(ti+r)*TS + tj + cc] += a[r][cc];
        }
    }
}

// ---------------- launch ----------------
extern "C" void kernel_launch(void* const* d_in, const int* in_sizes, int n_in,
                              void* d_out, int out_size)
{
    const float* hidden = (const float*)d_in[0];
    const float* Wq = (const float*)d_in[1];
    const float* Wk = (const float*)d_in[2];
    const float* Wv = (const float*)d_in[3];
    const float* Wo = (const float*)d_in[4];
    float* out = (float*)d_out;

    float *pq, *pk, *pv, *pocomb;
    cudaGetSymbolAddress((void**)&pq, g_q);
    cudaGetSymbolAddress((void**)&pk, g_k);
    cudaGetSymbolAddress((void**)&pv, g_v);
    cudaGetSymbolAddress((void**)&pocomb, g_ocomb);

    const long long OUT_E  = (long long)BX*NSEQ*HIDD;          // 4194304
    const long long ATTN_E = (long long)BX*HH*NSEQ*NSEQ;       // 67108864
    float* attn_out = nullptr;
    if ((long long)out_size >= OUT_E + ATTN_E) attn_out = out + OUT_E;

    cudaFuncSetAttribute(delta_pre_kernel,  cudaFuncAttributeMaxDynamicSharedMemorySize, 4*64*TS*4);
    cudaFuncSetAttribute(delta_scan_kernel, cudaFuncAttributeMaxDynamicSharedMemorySize, 5*64*TS*4);

    // 1. projections
    sgemm128<<<dim3(HIDD/128,   (BX*NSEQ)/128), 256>>>(hidden, Wq, pq, BX*NSEQ, HIDD,   HIDD);
    sgemm128<<<dim3((HKV*DD)/128,(BX*NSEQ)/128), 256>>>(hidden, Wk, pk, BX*NSEQ, HKV*DD, HIDD);
    sgemm128<<<dim3((HKV*DD)/128,(BX*NSEQ)/128), 256>>>(hidden, Wv, pv, BX*NSEQ, HKV*DD, HIDD);

    // 2. elementwise prep
    qsoftmax_kernel<<<(BX*NSEQ*HH)/8, 256>>>();
    kprep_kernel<<<(BX*NSEQ*HKV)/8, 256>>>();

    // 3. base attention (writes attn_weights + 0.5*o_base into ocomb)
    attn_kernel<<<dim3(NSEQ/8, HH, BX), 256>>>(attn_out);

    // 4. delta rule: parallel solve, then sequential scan (adds 0.5*o_lin into ocomb)
    delta_pre_kernel<<<BX*HKV*NC, 256, 4*64*TS*4>>>();
    delta_scan_kernel<<<BX*HH, 256, 5*64*TS*4>>>();

    // 5. output projection: out = (0.5*o_lin + 0.5*o_base) @ Wo
    sgemm128<<<dim3(HIDD/128, (BX*NSEQ)/128), 256>>>(pocomb, Wo, out, BX*NSEQ, HIDD, HIDD);
}